// round 2
// baseline (speedup 1.0000x reference)
#include <cuda_runtime.h>
#include <math.h>

// ---------------------------------------------------------------------------
// Problem constants
//   B=2, T=64, S=256, D=768, H=12, KV=4, HD=64, HID=2048, CAP=50, EPS=1e-6
//   M = B*T*S = 32768 tokens
// ---------------------------------------------------------------------------
#define MTOK 32768
#define DMODEL 768
#define KVDIM 256
#define HIDDIM 2048
#define NB 2
#define NT 64
#define NS 256
#define NH 12
#define NKV 4

// ---------------------------------------------------------------------------
// Scratch (device globals; no allocation allowed)
// ---------------------------------------------------------------------------
__device__ float g_h [MTOK * DMODEL];   // rmsnorm1(x)
__device__ float g_q [MTOK * DMODEL];   // q projection
__device__ float g_k [MTOK * KVDIM];    // k projection
__device__ float g_v [MTOK * KVDIM];    // v projection
__device__ float g_o [MTOK * DMODEL];   // attention output
__device__ float g_x1[MTOK * DMODEL];   // x + attn @ wo
__device__ float g_h2[MTOK * DMODEL];   // rmsnorm2(x1)
__device__ float g_u1[MTOK * HIDDIM];   // h2 @ w1 (then gated in-place)
__device__ float g_u2[MTOK * HIDDIM];   // h2 @ w2

// ---------------------------------------------------------------------------
// SGEMM: C[M,N] = A[M,K] @ B[K,N] (+ R[M,N] if R != nullptr)
// All of M % 128 == 0, N % 128 == 0, K % 8 == 0 hold for every call.
// 128x128 block tile, BK=8, 256 threads, 8x8 register tile.
// ---------------------------------------------------------------------------
__global__ __launch_bounds__(256) void sgemm_kernel(
    const float* __restrict__ A, const float* __restrict__ B,
    const float* __restrict__ R, float* __restrict__ C,
    int M, int N, int K) {
  __shared__ float As[8][128];
  __shared__ float Bs[8][128];
  const int tid = threadIdx.x;
  const int tx = tid & 15;         // 0..15 -> N direction
  const int ty = tid >> 4;         // 0..15 -> M direction
  const int bx = blockIdx.x;       // N tile
  const int by = blockIdx.y;       // M tile

  const float* Ab = A + (size_t)by * 128 * K;
  const float* Bb = B + (size_t)bx * 128;

  const int arow = tid >> 1;           // 0..127
  const int acol = (tid & 1) << 2;     // 0 or 4
  const int brow = tid >> 5;           // 0..7
  const int bcol = (tid & 31) << 2;    // 0..124

  float acc[8][8];
#pragma unroll
  for (int i = 0; i < 8; i++)
#pragma unroll
    for (int j = 0; j < 8; j++) acc[i][j] = 0.f;

  for (int k0 = 0; k0 < K; k0 += 8) {
    float4 av = *(const float4*)(Ab + (size_t)arow * K + k0 + acol);
    As[acol + 0][arow] = av.x;
    As[acol + 1][arow] = av.y;
    As[acol + 2][arow] = av.z;
    As[acol + 3][arow] = av.w;
    *(float4*)(&Bs[brow][bcol]) =
        *(const float4*)(Bb + (size_t)(k0 + brow) * N + bcol);
    __syncthreads();
#pragma unroll
    for (int kk = 0; kk < 8; kk++) {
      float4 a0 = *(const float4*)(&As[kk][ty * 8]);
      float4 a1 = *(const float4*)(&As[kk][ty * 8 + 4]);
      float4 b0 = *(const float4*)(&Bs[kk][tx * 8]);
      float4 b1 = *(const float4*)(&Bs[kk][tx * 8 + 4]);
      float ar[8] = {a0.x, a0.y, a0.z, a0.w, a1.x, a1.y, a1.z, a1.w};
      float br[8] = {b0.x, b0.y, b0.z, b0.w, b1.x, b1.y, b1.z, b1.w};
#pragma unroll
      for (int i = 0; i < 8; i++)
#pragma unroll
        for (int j = 0; j < 8; j++)
          acc[i][j] = fmaf(ar[i], br[j], acc[i][j]);
    }
    __syncthreads();
  }

  const size_t crow0 = (size_t)by * 128 + ty * 8;
  const int ccol0 = bx * 128 + tx * 8;
#pragma unroll
  for (int i = 0; i < 8; i++) {
    size_t base = (crow0 + i) * (size_t)N + ccol0;
    float4 c0 = {acc[i][0], acc[i][1], acc[i][2], acc[i][3]};
    float4 c1 = {acc[i][4], acc[i][5], acc[i][6], acc[i][7]};
    if (R) {
      float4 r0 = *(const float4*)(R + base);
      float4 r1 = *(const float4*)(R + base + 4);
      c0.x += r0.x; c0.y += r0.y; c0.z += r0.z; c0.w += r0.w;
      c1.x += r1.x; c1.y += r1.y; c1.z += r1.z; c1.w += r1.w;
    }
    *(float4*)(C + base) = c0;
    *(float4*)(C + base + 4) = c1;
  }
}

// ---------------------------------------------------------------------------
// Row RMSNorm over 768 (one block per row)
// ---------------------------------------------------------------------------
__global__ __launch_bounds__(256) void rmsnorm_kernel(
    const float* __restrict__ x, const float* __restrict__ w,
    float* __restrict__ out) {
  const int row = blockIdx.x;
  const float* xr = x + (size_t)row * DMODEL;
  float* orow = out + (size_t)row * DMODEL;
  const int tid = threadIdx.x;
  float v0 = xr[tid];
  float v1 = xr[tid + 256];
  float v2 = xr[tid + 512];
  float s = v0 * v0 + v1 * v1 + v2 * v2;
#pragma unroll
  for (int off = 16; off > 0; off >>= 1)
    s += __shfl_xor_sync(0xffffffffu, s, off);
  __shared__ float ws[8];
  if ((tid & 31) == 0) ws[tid >> 5] = s;
  __syncthreads();
  float tot = ws[0] + ws[1] + ws[2] + ws[3] + ws[4] + ws[5] + ws[6] + ws[7];
  float rs = rsqrtf(tot * (1.0f / (float)DMODEL) + 1e-6f);
  orow[tid]       = v0 * rs * w[tid];
  orow[tid + 256] = v1 * rs * w[tid + 256];
  orow[tid + 512] = v2 * rs * w[tid + 512];
}

// ---------------------------------------------------------------------------
// Per-head RMSNorm over 64 contiguous floats (QK-norm), in-place.
// One warp per head, 8 heads per 256-thread block.
// ---------------------------------------------------------------------------
__global__ __launch_bounds__(256) void headnorm_kernel(
    float* __restrict__ x, const float* __restrict__ w, int nheads) {
  int head = blockIdx.x * 8 + (threadIdx.x >> 5);
  if (head >= nheads) return;
  int lane = threadIdx.x & 31;
  float* p = x + (size_t)head * 64;
  float a = p[lane];
  float b = p[lane + 32];
  float s = a * a + b * b;
#pragma unroll
  for (int off = 16; off > 0; off >>= 1)
    s += __shfl_xor_sync(0xffffffffu, s, off);
  float rs = rsqrtf(s * (1.0f / 64.0f) + 1e-6f);
  p[lane]      = a * rs * w[lane];
  p[lane + 32] = b * rs * w[lane + 32];
}

// ---------------------------------------------------------------------------
// Attention: one block per (b, s, h). Causal over T=64, HD=64.
// logits = (Q K^T)/8, soft-capped at 50, causal masked, softmax, then P @ V.
// Smem reuse: Qs holds Q then P; Ks holds K then V.  2 * 64*65*4 = 33.3 KB.
// ---------------------------------------------------------------------------
__global__ __launch_bounds__(256) void attn_kernel(
    const float* __restrict__ q, const float* __restrict__ k,
    const float* __restrict__ v, float* __restrict__ o) {
  __shared__ float Qs[64][65];  // Q, then P
  __shared__ float Ks[64][65];  // K, then V
  const int idx = blockIdx.x;            // ((b*NS)+s)*NH + h
  const int h = idx % NH;
  const int s = (idx / NH) % NS;
  const int b = idx / (NH * NS);
  const int kvh = h / (NH / NKV);        // repeat_interleave mapping
  const int tid = threadIdx.x;

  // Load Q and K tiles
  for (int i = tid; i < 64 * 64; i += 256) {
    int t = i >> 6, d = i & 63;
    size_t tok = (size_t)((b * NT + t) * NS + s);
    Qs[t][d] = q[tok * DMODEL + h * 64 + d];
    Ks[t][d] = k[tok * KVDIM + kvh * 64 + d];
  }
  __syncthreads();

  const int row = tid >> 2;   // query frame 0..63
  const int tj  = tid & 3;    // column quarter

  float lg[16];
#pragma unroll
  for (int jj = 0; jj < 16; jj++) {
    int j = tj * 16 + jj;
    float acc = 0.f;
#pragma unroll 8
    for (int d = 0; d < 64; d++) acc += Qs[row][d] * Ks[j][d];
    acc *= 0.125f;                       // HD^-0.5
    acc = 50.0f * tanhf(acc * 0.02f);    // soft cap
    lg[jj] = (j <= row) ? acc : -INFINITY;
  }

  // row softmax across the 4-thread group (consecutive lanes)
  float mx = lg[0];
#pragma unroll
  for (int jj = 1; jj < 16; jj++) mx = fmaxf(mx, lg[jj]);
  mx = fmaxf(mx, __shfl_xor_sync(0xffffffffu, mx, 1));
  mx = fmaxf(mx, __shfl_xor_sync(0xffffffffu, mx, 2));
  float sum = 0.f;
#pragma unroll
  for (int jj = 0; jj < 16; jj++) {
    float e = __expf(lg[jj] - mx);   // exp(-inf)=0 handles the mask
    lg[jj] = e;
    sum += e;
  }
  sum += __shfl_xor_sync(0xffffffffu, sum, 1);
  sum += __shfl_xor_sync(0xffffffffu, sum, 2);
  float inv = 1.0f / sum;

  __syncthreads();  // everyone done reading Q/K
  // Store P into Qs; load V into Ks
#pragma unroll
  for (int jj = 0; jj < 16; jj++) Qs[row][tj * 16 + jj] = lg[jj] * inv;
  for (int i = tid; i < 64 * 64; i += 256) {
    int t = i >> 6, d = i & 63;
    size_t tok = (size_t)((b * NT + t) * NS + s);
    Ks[t][d] = v[tok * KVDIM + kvh * 64 + d];
  }
  __syncthreads();

  // O[row][tj*16 .. +15] = sum_j P[row][j] * V[j][d]
  float out[16];
#pragma unroll
  for (int dd = 0; dd < 16; dd++) out[dd] = 0.f;
  for (int j = 0; j < 64; j++) {
    float p = Qs[row][j];
#pragma unroll
    for (int dd = 0; dd < 16; dd++)
      out[dd] = fmaf(p, Ks[j][tj * 16 + dd], out[dd]);
  }
  size_t tok = (size_t)((b * NT + row) * NS + s);
#pragma unroll
  for (int dd = 0; dd < 16; dd++)
    o[tok * DMODEL + h * 64 + tj * 16 + dd] = out[dd];
}

// ---------------------------------------------------------------------------
// SwiGLU gate: u1 = silu(u1) * u2, elementwise (float4)
// ---------------------------------------------------------------------------
__global__ __launch_bounds__(256) void swiglu_kernel(
    float* __restrict__ u1, const float* __restrict__ u2) {
  size_t i = (size_t)blockIdx.x * 256 + threadIdx.x;
  float4 a = ((const float4*)u1)[i];
  float4 b = ((const float4*)u2)[i];
  a.x = a.x / (1.f + __expf(-a.x)) * b.x;
  a.y = a.y / (1.f + __expf(-a.y)) * b.y;
  a.z = a.z / (1.f + __expf(-a.z)) * b.z;
  a.w = a.w / (1.f + __expf(-a.w)) * b.w;
  ((float4*)u1)[i] = a;
}

// ---------------------------------------------------------------------------
// Launch
// ---------------------------------------------------------------------------
extern "C" void kernel_launch(void* const* d_in, const int* in_sizes, int n_in,
                              void* d_out, int out_size) {
  const float* x  = (const float*)d_in[0];
  const float* n1 = (const float*)d_in[1];
  const float* n2 = (const float*)d_in[2];
  const float* qn = (const float*)d_in[3];
  const float* kn = (const float*)d_in[4];
  const float* wq = (const float*)d_in[5];
  const float* wk = (const float*)d_in[6];
  const float* wv = (const float*)d_in[7];
  const float* wo = (const float*)d_in[8];
  const float* w1 = (const float*)d_in[9];
  const float* w2 = (const float*)d_in[10];
  const float* w3 = (const float*)d_in[11];
  float* out = (float*)d_out;

  float *h, *q, *k, *v, *o, *x1, *h2, *u1, *u2;
  cudaGetSymbolAddress((void**)&h,  g_h);
  cudaGetSymbolAddress((void**)&q,  g_q);
  cudaGetSymbolAddress((void**)&k,  g_k);
  cudaGetSymbolAddress((void**)&v,  g_v);
  cudaGetSymbolAddress((void**)&o,  g_o);
  cudaGetSymbolAddress((void**)&x1, g_x1);
  cudaGetSymbolAddress((void**)&h2, g_h2);
  cudaGetSymbolAddress((void**)&u1, g_u1);
  cudaGetSymbolAddress((void**)&u2, g_u2);

  // 1. h = rmsnorm(x) * norm1_w
  rmsnorm_kernel<<<MTOK, 256>>>(x, n1, h);

  // 2-4. QKV projections
  {
    dim3 gq(DMODEL / 128, MTOK / 128);
    sgemm_kernel<<<gq, 256>>>(h, wq, nullptr, q, MTOK, DMODEL, DMODEL);
    dim3 gkv(KVDIM / 128, MTOK / 128);
    sgemm_kernel<<<gkv, 256>>>(h, wk, nullptr, k, MTOK, KVDIM, DMODEL);
    sgemm_kernel<<<gkv, 256>>>(h, wv, nullptr, v, MTOK, KVDIM, DMODEL);
  }

  // 5-6. QK-norm (per 64-dim head, in place)
  headnorm_kernel<<<(MTOK * NH) / 8, 256>>>(q, qn, MTOK * NH);
  headnorm_kernel<<<(MTOK * NKV) / 8, 256>>>(k, kn, MTOK * NKV);

  // 7. attention
  attn_kernel<<<NB * NS * NH, 256>>>(q, k, v, o);

  // 8. x1 = x + o @ wo
  {
    dim3 g(DMODEL / 128, MTOK / 128);
    sgemm_kernel<<<g, 256>>>(o, wo, x, x1, MTOK, DMODEL, DMODEL);
  }

  // 9. h2 = rmsnorm(x1) * norm2_w
  rmsnorm_kernel<<<MTOK, 256>>>(x1, n2, h2);

  // 10-11. MLP up projections
  {
    dim3 g(HIDDIM / 128, MTOK / 128);
    sgemm_kernel<<<g, 256>>>(h2, w1, nullptr, u1, MTOK, HIDDIM, DMODEL);
    sgemm_kernel<<<g, 256>>>(h2, w2, nullptr, u2, MTOK, HIDDIM, DMODEL);
  }

  // 12. u1 = silu(u1) * u2
  swiglu_kernel<<<(MTOK * HIDDIM) / (256 * 4), 256>>>(u1, u2);

  // 13. out = x1 + u1 @ w3
  {
    dim3 g(DMODEL / 128, MTOK / 128);
    sgemm_kernel<<<g, 256>>>(u1, w3, x1, out, MTOK, DMODEL, HIDDIM);
  }
}

// round 3
// speedup vs baseline: 2.7600x; 2.7600x over previous
#include <cuda_runtime.h>
#include <math.h>
#include <stdint.h>

// ---------------------------------------------------------------------------
// Problem constants
//   B=2, T=64, S=256, D=768, H=12, KV=4, HD=64, HID=2048, CAP=50, EPS=1e-6
//   M = B*T*S = 32768 tokens
// ---------------------------------------------------------------------------
#define MTOK 32768
#define DMODEL 768
#define KVDIM 256
#define HIDDIM 2048
#define NB 2
#define NT 64
#define NS 256
#define NH 12
#define NKV 4

// ---------------------------------------------------------------------------
// Scratch (device globals; no allocation allowed)
// ---------------------------------------------------------------------------
__device__ float g_h [MTOK * DMODEL];   // rmsnorm1(x)
__device__ float g_q [MTOK * DMODEL];   // q projection
__device__ float g_k [MTOK * KVDIM];    // k projection
__device__ float g_v [MTOK * KVDIM];    // v projection
__device__ float g_o [MTOK * DMODEL];   // attention output
__device__ float g_x1[MTOK * DMODEL];   // x + attn @ wo
__device__ float g_h2[MTOK * DMODEL];   // rmsnorm2(x1)
__device__ float g_u1[MTOK * HIDDIM];   // h2 @ w1 (then gated in-place)
__device__ float g_u2[MTOK * HIDDIM];   // h2 @ w2

// ---------------------------------------------------------------------------
// tf32 helpers
// ---------------------------------------------------------------------------
__device__ __forceinline__ uint32_t f2tf32(float x) {
  uint32_t r;
  asm("cvt.rna.tf32.f32 %0, %1;" : "=r"(r) : "f"(x));
  return r;
}

__device__ __forceinline__ void mma_tf32(float* c, const uint32_t* a,
                                         const uint32_t* b) {
  asm volatile(
      "mma.sync.aligned.m16n8k8.row.col.f32.tf32.tf32.f32 "
      "{%0,%1,%2,%3}, {%4,%5,%6,%7}, {%8,%9}, {%0,%1,%2,%3};"
      : "+f"(c[0]), "+f"(c[1]), "+f"(c[2]), "+f"(c[3])
      : "r"(a[0]), "r"(a[1]), "r"(a[2]), "r"(a[3]), "r"(b[0]), "r"(b[1]));
}

// ---------------------------------------------------------------------------
// TF32 tensor-core GEMM: C[M,N] = A[M,K] @ B[K,N] (+ R if non-null)
// 128x128 block tile, BK=32, 256 threads (8 warps, 4M x 2N), warp tile 32x64.
// M%128==0, N%128==0, K%32==0 hold for every call here.
// ---------------------------------------------------------------------------
#define ASTRIDE 36   // 128 rows x (32 + 4) -> fragment loads conflict-free
#define BSTRIDE 136  // 32 rows  x (128 + 8) -> fragment loads conflict-free

__global__ __launch_bounds__(256, 2) void gemm_tf32_kernel(
    const float* __restrict__ A, const float* __restrict__ B,
    const float* __restrict__ R, float* __restrict__ C,
    int M, int N, int K) {
  __shared__ uint32_t As[128 * ASTRIDE];
  __shared__ uint32_t Bs[32 * BSTRIDE];

  const int tid = threadIdx.x;
  const int lane = tid & 31;
  const int warp = tid >> 5;
  const int wm = warp & 3;   // 0..3 -> M
  const int wn = warp >> 2;  // 0..1 -> N
  const int gid = lane >> 2;     // groupID 0..7
  const int tin = lane & 3;      // thread-in-group 0..3
  const int bx = blockIdx.x;
  const int by = blockIdx.y;

  const float* Ag = A + (size_t)by * 128 * K;
  const float* Bg = B + (size_t)bx * 128;

  float acc[2][8][4];
#pragma unroll
  for (int mi = 0; mi < 2; mi++)
#pragma unroll
    for (int ni = 0; ni < 8; ni++)
#pragma unroll
      for (int f = 0; f < 4; f++) acc[mi][ni][f] = 0.f;

  for (int k0 = 0; k0 < K; k0 += 32) {
    // --- stage A: 128x32 floats, 4 float4 per thread ---
#pragma unroll
    for (int r = 0; r < 4; r++) {
      int idx = tid + r * 256;
      int row = idx >> 3;
      int c4 = (idx & 7) << 2;
      float4 v = *(const float4*)(Ag + (size_t)row * K + k0 + c4);
      uint4 t = {f2tf32(v.x), f2tf32(v.y), f2tf32(v.z), f2tf32(v.w)};
      *(uint4*)(&As[row * ASTRIDE + c4]) = t;
    }
    // --- stage B: 32x128 floats, 4 float4 per thread ---
#pragma unroll
    for (int r = 0; r < 4; r++) {
      int idx = tid + r * 256;
      int row = idx >> 5;
      int c4 = (idx & 31) << 2;
      float4 v = *(const float4*)(Bg + (size_t)(k0 + row) * N + c4);
      uint4 t = {f2tf32(v.x), f2tf32(v.y), f2tf32(v.z), f2tf32(v.w)};
      *(uint4*)(&Bs[row * BSTRIDE + c4]) = t;
    }
    __syncthreads();

#pragma unroll
    for (int kt = 0; kt < 4; kt++) {
      const int kc = kt * 8;
      uint32_t af[2][4];
#pragma unroll
      for (int mi = 0; mi < 2; mi++) {
        int row = wm * 32 + mi * 16 + gid;
        af[mi][0] = As[row * ASTRIDE + kc + tin];
        af[mi][1] = As[(row + 8) * ASTRIDE + kc + tin];
        af[mi][2] = As[row * ASTRIDE + kc + tin + 4];
        af[mi][3] = As[(row + 8) * ASTRIDE + kc + tin + 4];
      }
      uint32_t bf[8][2];
#pragma unroll
      for (int ni = 0; ni < 8; ni++) {
        int col = wn * 64 + ni * 8 + gid;
        bf[ni][0] = Bs[(kc + tin) * BSTRIDE + col];
        bf[ni][1] = Bs[(kc + tin + 4) * BSTRIDE + col];
      }
#pragma unroll
      for (int mi = 0; mi < 2; mi++)
#pragma unroll
        for (int ni = 0; ni < 8; ni++)
          mma_tf32(acc[mi][ni], af[mi], bf[ni]);
    }
    __syncthreads();
  }

  // --- epilogue ---
#pragma unroll
  for (int mi = 0; mi < 2; mi++) {
#pragma unroll
    for (int ni = 0; ni < 8; ni++) {
      int row = by * 128 + wm * 32 + mi * 16 + gid;
      int col = bx * 128 + wn * 64 + ni * 8 + (tin << 1);
      size_t o0 = (size_t)row * N + col;
      size_t o1 = (size_t)(row + 8) * N + col;
      float2 v0 = {acc[mi][ni][0], acc[mi][ni][1]};
      float2 v1 = {acc[mi][ni][2], acc[mi][ni][3]};
      if (R) {
        float2 r0 = *(const float2*)(R + o0);
        float2 r1 = *(const float2*)(R + o1);
        v0.x += r0.x; v0.y += r0.y;
        v1.x += r1.x; v1.y += r1.y;
      }
      *(float2*)(C + o0) = v0;
      *(float2*)(C + o1) = v1;
    }
  }
}

// ---------------------------------------------------------------------------
// Row RMSNorm over 768 (one block per row)
// ---------------------------------------------------------------------------
__global__ __launch_bounds__(256) void rmsnorm_kernel(
    const float* __restrict__ x, const float* __restrict__ w,
    float* __restrict__ out) {
  const int row = blockIdx.x;
  const float* xr = x + (size_t)row * DMODEL;
  float* orow = out + (size_t)row * DMODEL;
  const int tid = threadIdx.x;
  float v0 = xr[tid];
  float v1 = xr[tid + 256];
  float v2 = xr[tid + 512];
  float s = v0 * v0 + v1 * v1 + v2 * v2;
#pragma unroll
  for (int off = 16; off > 0; off >>= 1)
    s += __shfl_xor_sync(0xffffffffu, s, off);
  __shared__ float ws[8];
  if ((tid & 31) == 0) ws[tid >> 5] = s;
  __syncthreads();
  float tot = ws[0] + ws[1] + ws[2] + ws[3] + ws[4] + ws[5] + ws[6] + ws[7];
  float rs = rsqrtf(tot * (1.0f / (float)DMODEL) + 1e-6f);
  orow[tid]       = v0 * rs * w[tid];
  orow[tid + 256] = v1 * rs * w[tid + 256];
  orow[tid + 512] = v2 * rs * w[tid + 512];
}

// ---------------------------------------------------------------------------
// Per-head RMSNorm over 64 contiguous floats (QK-norm), in-place.
// ---------------------------------------------------------------------------
__global__ __launch_bounds__(256) void headnorm_kernel(
    float* __restrict__ x, const float* __restrict__ w, int nheads) {
  int head = blockIdx.x * 8 + (threadIdx.x >> 5);
  if (head >= nheads) return;
  int lane = threadIdx.x & 31;
  float* p = x + (size_t)head * 64;
  float a = p[lane];
  float b = p[lane + 32];
  float s = a * a + b * b;
#pragma unroll
  for (int off = 16; off > 0; off >>= 1)
    s += __shfl_xor_sync(0xffffffffu, s, off);
  float rs = rsqrtf(s * (1.0f / 64.0f) + 1e-6f);
  p[lane]      = a * rs * w[lane];
  p[lane + 32] = b * rs * w[lane + 32];
}

// ---------------------------------------------------------------------------
// Attention: one block per (b, s, h). Causal over T=64, HD=64.
// ---------------------------------------------------------------------------
__global__ __launch_bounds__(256) void attn_kernel(
    const float* __restrict__ q, const float* __restrict__ k,
    const float* __restrict__ v, float* __restrict__ o) {
  __shared__ float Qs[64][65];  // Q, then P
  __shared__ float Ks[64][65];  // K, then V
  const int idx = blockIdx.x;            // ((b*NS)+s)*NH + h
  const int h = idx % NH;
  const int s = (idx / NH) % NS;
  const int b = idx / (NH * NS);
  const int kvh = h / (NH / NKV);
  const int tid = threadIdx.x;

  for (int i = tid; i < 64 * 64; i += 256) {
    int t = i >> 6, d = i & 63;
    size_t tok = (size_t)((b * NT + t) * NS + s);
    Qs[t][d] = q[tok * DMODEL + h * 64 + d];
    Ks[t][d] = k[tok * KVDIM + kvh * 64 + d];
  }
  __syncthreads();

  const int row = tid >> 2;
  const int tj  = tid & 3;

  float lg[16];
#pragma unroll
  for (int jj = 0; jj < 16; jj++) {
    int j = tj * 16 + jj;
    float acc = 0.f;
#pragma unroll 8
    for (int d = 0; d < 64; d++) acc += Qs[row][d] * Ks[j][d];
    acc *= 0.125f;
    acc = 50.0f * tanhf(acc * 0.02f);
    lg[jj] = (j <= row) ? acc : -INFINITY;
  }

  float mx = lg[0];
#pragma unroll
  for (int jj = 1; jj < 16; jj++) mx = fmaxf(mx, lg[jj]);
  mx = fmaxf(mx, __shfl_xor_sync(0xffffffffu, mx, 1));
  mx = fmaxf(mx, __shfl_xor_sync(0xffffffffu, mx, 2));
  float sum = 0.f;
#pragma unroll
  for (int jj = 0; jj < 16; jj++) {
    float e = __expf(lg[jj] - mx);
    lg[jj] = e;
    sum += e;
  }
  sum += __shfl_xor_sync(0xffffffffu, sum, 1);
  sum += __shfl_xor_sync(0xffffffffu, sum, 2);
  float inv = 1.0f / sum;

  __syncthreads();
#pragma unroll
  for (int jj = 0; jj < 16; jj++) Qs[row][tj * 16 + jj] = lg[jj] * inv;
  for (int i = tid; i < 64 * 64; i += 256) {
    int t = i >> 6, d = i & 63;
    size_t tok = (size_t)((b * NT + t) * NS + s);
    Ks[t][d] = v[tok * KVDIM + kvh * 64 + d];
  }
  __syncthreads();

  float out[16];
#pragma unroll
  for (int dd = 0; dd < 16; dd++) out[dd] = 0.f;
  for (int j = 0; j < 64; j++) {
    float p = Qs[row][j];
#pragma unroll
    for (int dd = 0; dd < 16; dd++)
      out[dd] = fmaf(p, Ks[j][tj * 16 + dd], out[dd]);
  }
  size_t tok = (size_t)((b * NT + row) * NS + s);
#pragma unroll
  for (int dd = 0; dd < 16; dd++)
    o[tok * DMODEL + h * 64 + tj * 16 + dd] = out[dd];
}

// ---------------------------------------------------------------------------
// SwiGLU gate: u1 = silu(u1) * u2
// ---------------------------------------------------------------------------
__global__ __launch_bounds__(256) void swiglu_kernel(
    float* __restrict__ u1, const float* __restrict__ u2) {
  size_t i = (size_t)blockIdx.x * 256 + threadIdx.x;
  float4 a = ((const float4*)u1)[i];
  float4 b = ((const float4*)u2)[i];
  a.x = a.x / (1.f + __expf(-a.x)) * b.x;
  a.y = a.y / (1.f + __expf(-a.y)) * b.y;
  a.z = a.z / (1.f + __expf(-a.z)) * b.z;
  a.w = a.w / (1.f + __expf(-a.w)) * b.w;
  ((float4*)u1)[i] = a;
}

// ---------------------------------------------------------------------------
// Launch
// ---------------------------------------------------------------------------
extern "C" void kernel_launch(void* const* d_in, const int* in_sizes, int n_in,
                              void* d_out, int out_size) {
  const float* x  = (const float*)d_in[0];
  const float* n1 = (const float*)d_in[1];
  const float* n2 = (const float*)d_in[2];
  const float* qn = (const float*)d_in[3];
  const float* kn = (const float*)d_in[4];
  const float* wq = (const float*)d_in[5];
  const float* wk = (const float*)d_in[6];
  const float* wv = (const float*)d_in[7];
  const float* wo = (const float*)d_in[8];
  const float* w1 = (const float*)d_in[9];
  const float* w2 = (const float*)d_in[10];
  const float* w3 = (const float*)d_in[11];
  float* out = (float*)d_out;

  float *h, *q, *k, *v, *o, *x1, *h2, *u1, *u2;
  cudaGetSymbolAddress((void**)&h,  g_h);
  cudaGetSymbolAddress((void**)&q,  g_q);
  cudaGetSymbolAddress((void**)&k,  g_k);
  cudaGetSymbolAddress((void**)&v,  g_v);
  cudaGetSymbolAddress((void**)&o,  g_o);
  cudaGetSymbolAddress((void**)&x1, g_x1);
  cudaGetSymbolAddress((void**)&h2, g_h2);
  cudaGetSymbolAddress((void**)&u1, g_u1);
  cudaGetSymbolAddress((void**)&u2, g_u2);

  // 1. h = rmsnorm(x) * norm1_w
  rmsnorm_kernel<<<MTOK, 256>>>(x, n1, h);

  // 2-4. QKV projections (tf32 tensor cores)
  {
    dim3 gq(DMODEL / 128, MTOK / 128);
    gemm_tf32_kernel<<<gq, 256>>>(h, wq, nullptr, q, MTOK, DMODEL, DMODEL);
    dim3 gkv(KVDIM / 128, MTOK / 128);
    gemm_tf32_kernel<<<gkv, 256>>>(h, wk, nullptr, k, MTOK, KVDIM, DMODEL);
    gemm_tf32_kernel<<<gkv, 256>>>(h, wv, nullptr, v, MTOK, KVDIM, DMODEL);
  }

  // 5-6. QK-norm
  headnorm_kernel<<<(MTOK * NH) / 8, 256>>>(q, qn, MTOK * NH);
  headnorm_kernel<<<(MTOK * NKV) / 8, 256>>>(k, kn, MTOK * NKV);

  // 7. attention
  attn_kernel<<<NB * NS * NH, 256>>>(q, k, v, o);

  // 8. x1 = x + o @ wo
  {
    dim3 g(DMODEL / 128, MTOK / 128);
    gemm_tf32_kernel<<<g, 256>>>(o, wo, x, x1, MTOK, DMODEL, DMODEL);
  }

  // 9. h2 = rmsnorm(x1) * norm2_w
  rmsnorm_kernel<<<MTOK, 256>>>(x1, n2, h2);

  // 10-11. MLP up projections
  {
    dim3 g(HIDDIM / 128, MTOK / 128);
    gemm_tf32_kernel<<<g, 256>>>(h2, w1, nullptr, u1, MTOK, HIDDIM, DMODEL);
    gemm_tf32_kernel<<<g, 256>>>(h2, w2, nullptr, u2, MTOK, HIDDIM, DMODEL);
  }

  // 12. u1 = silu(u1) * u2
  swiglu_kernel<<<(MTOK * HIDDIM) / (256 * 4), 256>>>(u1, u2);

  // 13. out = x1 + u1 @ w3
  {
    dim3 g(DMODEL / 128, MTOK / 128);
    gemm_tf32_kernel<<<g, 256>>>(u1, w3, x1, out, MTOK, DMODEL, HIDDIM);
  }
}